// round 17
// baseline (speedup 1.0000x reference)
#include <cuda_runtime.h>
#include <cuda_fp16.h>
#include <cstdint>

// Quanvolution (2x2, 4 qubits): Zq = cos(pi*a_q + w_q);
//   ch0 = Z1*Z2*Z3, ch1 = Z0*Z1, ch2 = Z0*Z1*Z2, ch3 = Z0*Z1*Z2*Z3
//
// R17 = R16 algorithm (fp16 interleaved tables, shift-aligned STG.128 with
// per-channel shift s=(x-ch)&3, edge scalar pass) restructured as a single
// 512-thread block with every stage SINGLE-PASS: loader 504 slots, consumer
// 440 tasks, edges 96. Deleting the per-pass register arrays drops the live
// set so launch_bounds(512,4) (32-reg cap) reaches 100% theoretical occupancy.

#define H_IN 224
#define W_IN 224
#define L_OUT 223
#define PLANE 49729            // 223*223
#define RPB 8                  // output rows per block
#define TIR 9                  // input rows per block (halo)
#define TPITCH 224             // half2 words per table row
#define PI_F 3.14159265358979323846f

#define CASE_STORE(PTR, S, E)                                              \
    do {                                                                   \
        switch (S) {                                                       \
        case 0: *reinterpret_cast<float4*>((PTR) + 0) =                    \
                    make_float4(E(0), E(1), E(2), E(3)); break;            \
        case 1: *reinterpret_cast<float4*>((PTR) + 1) =                    \
                    make_float4(E(1), E(2), E(3), E(4)); break;            \
        case 2: *reinterpret_cast<float4*>((PTR) + 2) =                    \
                    make_float4(E(2), E(3), E(4), E(5)); break;            \
        default: *reinterpret_cast<float4*>((PTR) + 3) =                   \
                    make_float4(E(3), E(4), E(5), E(6)); break;            \
        }                                                                  \
    } while (0)

__global__ __launch_bounds__(512, 4) void quanv_main_kernel(
    const float* __restrict__ in,   // (64,1,224,224)
    const float* __restrict__ w,    // (1,4)
    float* __restrict__ out)        // (64,4,223,223)
{
    __shared__ __half2 T01[TIR * TPITCH];   // 8064 B
    __shared__ __half2 T23[TIR * TPITCH];   // 8064 B
    __shared__ float wtr[8];

    const int tid = threadIdx.x;
    const int ib  = blockIdx.x;      // 0..27
    const int b   = blockIdx.y;
    const int X   = ib * RPB;

    const float* inb = in + (size_t)b * (H_IN * W_IN);

    if (tid < 4) {
        float s, c;
        __sincosf(__ldg(&w[tid]), &s, &c);
        wtr[tid] = c; wtr[4 + tid] = s;
    }

    // ---- Batched input loads: single pass, 504 slots.
    //      r = tid/56 in [0,9), g = tid%56; float4 at (row X+r, col 4g)
    //      + scalar at col 4g+4 (for the c+1 interleave).
    float4 vv;
    float vx = 0.0f;
    int rr = 0, gg = 0;
    const bool act = (tid < 504);
    if (act) {
        rr = tid / 56;
        gg = tid - 56 * rr;
        int gr = X + rr; if (gr > 223) gr = 223;
        const float* rp = inb + gr * W_IN + 4 * gg;
        vv = *reinterpret_cast<const float4*>(rp);
        int c4 = 4 * gg + 4; if (c4 > 223) c4 = 223;
        vx = __ldg(&inb[gr * W_IN + c4]);
    }
    __syncthreads();   // weights ready

    const float cw0 = wtr[0], cw1 = wtr[1], cw2 = wtr[2], cw3 = wtr[3];
    const float sw0 = wtr[4], sw1 = wtr[5], sw2 = wtr[6], sw3 = wtr[7];

    // ---- Fold + pack + STS.128 (single pass).
    if (act) {
        float vs[5] = {vv.x, vv.y, vv.z, vv.w, vx};
        float sn[5], cs[5];
        #pragma unroll
        for (int j = 0; j < 5; j++) __sincosf(vs[j] * PI_F, &sn[j], &cs[j]);
        __half2 w01[4], w23[4];
        #pragma unroll
        for (int j = 0; j < 4; j++) {
            const float z0 = fmaf(-sn[j],     sw0, cs[j]     * cw0);
            const float z1 = fmaf(-sn[j + 1], sw1, cs[j + 1] * cw1);
            const float z2 = fmaf(-sn[j],     sw2, cs[j]     * cw2);
            const float z3 = fmaf(-sn[j + 1], sw3, cs[j + 1] * cw3);
            w01[j] = __floats2half2_rn(z0, z1);
            w23[j] = __floats2half2_rn(z2, z3);
        }
        const int base = rr * TPITCH + 4 * gg;
        *reinterpret_cast<uint4*>(&T01[base]) = *reinterpret_cast<uint4*>(w01);
        *reinterpret_cast<uint4*>(&T23[base]) = *reinterpret_cast<uint4*>(w23);
    }
    __syncthreads();   // tables ready

    const size_t obase = (size_t)b * 4 * PLANE;

    // ---- Quad consumer: single pass. rx = tid>>6 in [0,8), q = tid&63 < 55.
    {
        const int rx = tid >> 6;
        const int q  = tid & 63;
        const int x  = X + rx;
        if (q < 55 && x < L_OUT) {
            const int tb = rx * TPITCH + 4 * q;
            const uint4 a0 = *reinterpret_cast<const uint4*>(&T01[tb]);
            const uint4 a1 = *reinterpret_cast<const uint4*>(&T01[tb + 4]);
            const uint4 b0 = *reinterpret_cast<const uint4*>(&T23[tb + TPITCH]);
            const uint4 b1 = *reinterpret_cast<const uint4*>(&T23[tb + TPITCH + 4]);
            const uint32_t aw[8] = {a0.x, a0.y, a0.z, a0.w, a1.x, a1.y, a1.z, a1.w};
            const uint32_t bw[8] = {b0.x, b0.y, b0.z, b0.w, b1.x, b1.y, b1.z, b1.w};

            float p01[7], p23[7], z1v[7], z2v[7];
            #pragma unroll
            for (int i = 0; i < 7; i++) {
                const float2 z01 = __half22float2(*reinterpret_cast<const __half2*>(&aw[i]));
                const float2 z23 = __half22float2(*reinterpret_cast<const __half2*>(&bw[i]));
                p01[i] = z01.x * z01.y;
                p23[i] = z23.x * z23.y;
                z1v[i] = z01.y;
                z2v[i] = z23.x;
            }

            float* ob = out + obase + (size_t)x * L_OUT + 4 * q;
            int s;
            #define E0(i) (z1v[i] * p23[i])
            #define E1(i) (p01[i])
            #define E2(i) (p01[i] * z2v[i])
            #define E3(i) (p01[i] * p23[i])
            s = x & 3;        CASE_STORE(ob,             s, E0);   // ch0
            s = (x - 1) & 3;  CASE_STORE(ob + PLANE,     s, E1);   // ch1
            s = (x - 2) & 3;  CASE_STORE(ob + 2 * PLANE, s, E2);   // ch2
            s = (x - 3) & 3;  CASE_STORE(ob + 3 * PLANE, s, E3);   // ch3
            #undef E0
            #undef E1
            #undef E2
            #undef E3
        }
    }

    // ---- Edge scalars: per (row, ch) head y in [0,s) and tail [220+s, 223).
    if (tid < 128) {
        const int r = tid >> 4;          // 0..7
        const int e = tid & 15;
        if (e < 12) {
            const int ch = e & 3;
            const int k  = e >> 2;       // 0..2
            const int x  = X + r;
            if (x < L_OUT) {
                const int s = (x - ch) & 3;
                const int y = (k < s) ? k : (220 + k);
                const float2 z01 = __half22float2(T01[r * TPITCH + y]);
                const float2 z23 = __half22float2(T23[(r + 1) * TPITCH + y]);
                const float p01 = z01.x * z01.y;
                const float p23 = z23.x * z23.y;
                float val;
                if (ch == 0)      val = z01.y * p23;
                else if (ch == 1) val = p01;
                else if (ch == 2) val = p01 * z23.x;
                else              val = p01 * p23;
                out[obase + (size_t)ch * PLANE + (size_t)x * L_OUT + y] = val;
            }
        }
    }
}

extern "C" void kernel_launch(void* const* d_in, const int* in_sizes, int n_in,
                              void* d_out, int out_size) {
    const float* inputs = (const float*)d_in[0];   // (64,1,224,224) float32
    const float* weight = (const float*)d_in[1];   // (1,4) float32
    float* out = (float*)d_out;                    // (64,4,223,223) float32

    dim3 grid(28, 64);    // 28 row-groups x 64 batch
    quanv_main_kernel<<<grid, 512>>>(inputs, weight, out);
}